// round 8
// baseline (speedup 1.0000x reference)
#include <cuda_runtime.h>
#include <cstdint>

// Volume: 256^3 voxels. Inputs (metadata order):
//   d_in[0] vessel_labels  int32   [16777216]
//   d_in[1] id_intensity   float32 [256]
//   d_in[2] id_is_dark     int32   [256]
//   d_in[3] parenchyma     float32 [16777216]
// Output (float32, 67108864): out [16.78M] then onehot [3,16.78M]
//   ch0 = background, ch1 = dark vessel, ch2 = bright vessel.

#define N_VOX (256u * 256u * 256u)
#define VEC   (N_VOX / 4u)             // 4,194,304 vec4 elements
#define TPB   256u
#define ITEMS 2u                       // vec4 tiles per thread
#define BLOCKS (VEC / (TPB * ITEMS))   // 8192

__global__ __launch_bounds__(TPB, 8)
void yibei_kernel(const int4* __restrict__ labels4,
                  const float4* __restrict__ par4,
                  const float* __restrict__ id_intensity,
                  const int* __restrict__ id_is_dark,
                  float* __restrict__ out)
{
    // Fused LUT in shared: .x = intensity bits (id 0 forced to 1.0f), .y = dark flag
    __shared__ uint2 s_lut[256];
    {
        int t = threadIdx.x;   // blockDim.x == 256
        float inten = (t == 0) ? 1.0f : __ldg(&id_intensity[t]);
        s_lut[t] = make_uint2(__float_as_uint(inten), (unsigned)__ldg(&id_is_dark[t]));
    }
    __syncthreads();

    // Two contiguous-per-warp tiles, TPB apart: all accesses 128B-coalesced,
    // and per-stream store pairs form 1KB-contiguous warp bursts.
    unsigned base = blockIdx.x * (TPB * ITEMS) + threadIdx.x;
    unsigned i0 = base;
    unsigned i1 = base + TPB;

    // Inputs are single-use: stream them (evict-first), keep L2 free for writes.
    int4   lab0 = __ldcs(&labels4[i0]);
    int4   lab1 = __ldcs(&labels4[i1]);
    float4 p0   = __ldcs(&par4[i0]);
    float4 p1   = __ldcs(&par4[i1]);

    // Per-lane classification, kept in registers after unroll.
    float s0[4], s1[4];
    bool  m0[4], m1[4], d0[4], d1[4];
    #pragma unroll
    for (int k = 0; k < 4; ++k) {
        int l0 = (&lab0.x)[k];
        int l1 = (&lab1.x)[k];
        uint2 e0 = s_lut[l0];
        uint2 e1 = s_lut[l1];
        s0[k] = __uint_as_float(e0.x);   // lut[0] == 1.0 -> branch-free scale
        s1[k] = __uint_as_float(e1.x);
        m0[k] = (l0 != 0);               m1[k] = (l1 != 0);
        d0[k] = m0[k] & (e0.y == 1u);    d1[k] = m1[k] & (e1.y == 1u);
    }

    float4* o4 = (float4*)out;
    float4 a, b;

    // Stores use DEFAULT policy (write-back/allocate): L2 aggregates sectors
    // into full lines and drains writebacks in larger ordered bursts.

    // Stream 0: scaled parenchyma (grouped: both tiles back-to-back)
    #pragma unroll
    for (int k = 0; k < 4; ++k) { (&a.x)[k] = (&p0.x)[k] * s0[k];
                                  (&b.x)[k] = (&p1.x)[k] * s1[k]; }
    o4[i0] = a;
    o4[i1] = b;

    // Stream 1: background channel
    #pragma unroll
    for (int k = 0; k < 4; ++k) { (&a.x)[k] = m0[k] ? 0.0f : 1.0f;
                                  (&b.x)[k] = m1[k] ? 0.0f : 1.0f; }
    o4[VEC + i0] = a;
    o4[VEC + i1] = b;

    // Stream 2: dark-vessel channel
    #pragma unroll
    for (int k = 0; k < 4; ++k) { (&a.x)[k] = d0[k] ? 1.0f : 0.0f;
                                  (&b.x)[k] = d1[k] ? 1.0f : 0.0f; }
    o4[2u * VEC + i0] = a;
    o4[2u * VEC + i1] = b;

    // Stream 3: bright-vessel channel
    #pragma unroll
    for (int k = 0; k < 4; ++k) { (&a.x)[k] = (m0[k] & !d0[k]) ? 1.0f : 0.0f;
                                  (&b.x)[k] = (m1[k] & !d1[k]) ? 1.0f : 0.0f; }
    o4[3u * VEC + i0] = a;
    o4[3u * VEC + i1] = b;
}

extern "C" void kernel_launch(void* const* d_in, const int* in_sizes, int n_in,
                              void* d_out, int out_size)
{
    const int4*   labels4 = (const int4*)d_in[0];
    const float*  id_int  = (const float*)d_in[1];
    const int*    id_dark = (const int*)d_in[2];
    const float4* par4    = (const float4*)d_in[3];
    float*        out     = (float*)d_out;

    yibei_kernel<<<BLOCKS, TPB>>>(labels4, par4, id_int, id_dark, out);
}

// round 9
// speedup vs baseline: 1.0049x; 1.0049x over previous
#include <cuda_runtime.h>
#include <cstdint>

// Volume: 256^3 voxels. Inputs (metadata order):
//   d_in[0] vessel_labels  int32   [16777216]
//   d_in[1] id_intensity   float32 [256]
//   d_in[2] id_is_dark     int32   [256]
//   d_in[3] parenchyma     float32 [16777216]
// Output (float32, 67108864): out [16.78M] then onehot [3,16.78M]
//   ch0 = background, ch1 = dark vessel, ch2 = bright vessel.
//
// Final config (R9): HBM-bound at the mixed read/write ceiling (~5.8 TB/s
// counter-level). 2 vec4 tiles/thread, per-stream grouped __stcs stores
// (1KB contiguous warp bursts per output stream), __ldcs streaming loads,
// 32 regs, full occupancy.

#define N_VOX (256u * 256u * 256u)
#define VEC   (N_VOX / 4u)             // 4,194,304 vec4 elements
#define TPB   512u
#define ITEMS 2u                       // vec4 tiles per thread
#define BLOCKS (VEC / (TPB * ITEMS))   // 4096

__global__ __launch_bounds__(TPB, 4)
void yibei_kernel(const int4* __restrict__ labels4,
                  const float4* __restrict__ par4,
                  const float* __restrict__ id_intensity,
                  const int* __restrict__ id_is_dark,
                  float* __restrict__ out)
{
    // Fused LUT in shared: .x = intensity bits (id 0 forced to 1.0f), .y = dark flag
    __shared__ uint2 s_lut[256];
    if (threadIdx.x < 256u) {
        int t = threadIdx.x;
        float inten = (t == 0) ? 1.0f : __ldg(&id_intensity[t]);
        s_lut[t] = make_uint2(__float_as_uint(inten), (unsigned)__ldg(&id_is_dark[t]));
    }
    __syncthreads();

    // Two contiguous-per-warp tiles, TPB apart: all accesses 128B-coalesced,
    // and per-stream store pairs form 1KB-contiguous warp bursts.
    unsigned base = blockIdx.x * (TPB * ITEMS) + threadIdx.x;
    unsigned i0 = base;
    unsigned i1 = base + TPB;

    // Front-batch all global loads (MLP = 4), streaming policy.
    int4   lab0 = __ldcs(&labels4[i0]);
    int4   lab1 = __ldcs(&labels4[i1]);
    float4 p0   = __ldcs(&par4[i0]);
    float4 p1   = __ldcs(&par4[i1]);

    // Per-lane classification, kept in registers after unroll.
    float s0[4], s1[4];
    bool  m0[4], m1[4], d0[4], d1[4];
    #pragma unroll
    for (int k = 0; k < 4; ++k) {
        int l0 = (&lab0.x)[k];
        int l1 = (&lab1.x)[k];
        uint2 e0 = s_lut[l0];
        uint2 e1 = s_lut[l1];
        s0[k] = __uint_as_float(e0.x);   // lut[0] == 1.0 -> branch-free scale
        s1[k] = __uint_as_float(e1.x);
        m0[k] = (l0 != 0);               m1[k] = (l1 != 0);
        d0[k] = m0[k] & (e0.y == 1u);    d1[k] = m1[k] & (e1.y == 1u);
    }

    float4* o4 = (float4*)out;
    float4 a, b;

    // Stream 0: scaled parenchyma (grouped: both tiles back-to-back)
    #pragma unroll
    for (int k = 0; k < 4; ++k) { (&a.x)[k] = (&p0.x)[k] * s0[k];
                                  (&b.x)[k] = (&p1.x)[k] * s1[k]; }
    __stcs(&o4[i0], a);
    __stcs(&o4[i1], b);

    // Stream 1: background channel
    #pragma unroll
    for (int k = 0; k < 4; ++k) { (&a.x)[k] = m0[k] ? 0.0f : 1.0f;
                                  (&b.x)[k] = m1[k] ? 0.0f : 1.0f; }
    __stcs(&o4[VEC + i0], a);
    __stcs(&o4[VEC + i1], b);

    // Stream 2: dark-vessel channel
    #pragma unroll
    for (int k = 0; k < 4; ++k) { (&a.x)[k] = d0[k] ? 1.0f : 0.0f;
                                  (&b.x)[k] = d1[k] ? 1.0f : 0.0f; }
    __stcs(&o4[2u * VEC + i0], a);
    __stcs(&o4[2u * VEC + i1], b);

    // Stream 3: bright-vessel channel
    #pragma unroll
    for (int k = 0; k < 4; ++k) { (&a.x)[k] = (m0[k] & !d0[k]) ? 1.0f : 0.0f;
                                  (&b.x)[k] = (m1[k] & !d1[k]) ? 1.0f : 0.0f; }
    __stcs(&o4[3u * VEC + i0], a);
    __stcs(&o4[3u * VEC + i1], b);
}

extern "C" void kernel_launch(void* const* d_in, const int* in_sizes, int n_in,
                              void* d_out, int out_size)
{
    const int4*   labels4 = (const int4*)d_in[0];
    const float*  id_int  = (const float*)d_in[1];
    const int*    id_dark = (const int*)d_in[2];
    const float4* par4    = (const float4*)d_in[3];
    float*        out     = (float*)d_out;

    yibei_kernel<<<BLOCKS, TPB>>>(labels4, par4, id_int, id_dark, out);
}

// round 10
// speedup vs baseline: 1.0250x; 1.0200x over previous
#include <cuda_runtime.h>
#include <cstdint>

// Volume: 256^3 voxels. Inputs (metadata order):
//   d_in[0] vessel_labels  int32   [16777216]
//   d_in[1] id_intensity   float32 [256]
//   d_in[2] id_is_dark     int32   [256]
//   d_in[3] parenchyma     float32 [16777216]
// Output (float32, 67108864): out [16.78M] then onehot [3,16.78M]
//   ch0 = background, ch1 = dark vessel, ch2 = bright vessel.
//
// FINAL (R10 = R5 config): workload is hard HBM-bound — 128 MB reads +
// 256 MB writes irreducible. Best-measured config across 9 rounds:
// TPB=256, 2 vec4 tiles/thread, per-stream grouped __stcs stores (1KB
// contiguous warp burst per output stream), __ldcs streaming loads,
// 32 regs, occ ~85%, DRAM ~73.5% (ncu 59.2 us).

#define N_VOX (256u * 256u * 256u)
#define VEC   (N_VOX / 4u)             // 4,194,304 vec4 elements
#define TPB   256u
#define ITEMS 2u                       // vec4 tiles per thread
#define BLOCKS (VEC / (TPB * ITEMS))   // 8192

__global__ __launch_bounds__(TPB, 8)
void yibei_kernel(const int4* __restrict__ labels4,
                  const float4* __restrict__ par4,
                  const float* __restrict__ id_intensity,
                  const int* __restrict__ id_is_dark,
                  float* __restrict__ out)
{
    // Fused LUT in shared: .x = intensity bits (id 0 forced to 1.0f), .y = dark flag
    __shared__ uint2 s_lut[256];
    {
        int t = threadIdx.x;   // blockDim.x == 256
        float inten = (t == 0) ? 1.0f : __ldg(&id_intensity[t]);
        s_lut[t] = make_uint2(__float_as_uint(inten), (unsigned)__ldg(&id_is_dark[t]));
    }
    __syncthreads();

    // Two contiguous-per-warp tiles, TPB apart: all accesses 128B-coalesced,
    // and per-stream store pairs form 1KB-contiguous warp bursts.
    unsigned base = blockIdx.x * (TPB * ITEMS) + threadIdx.x;
    unsigned i0 = base;
    unsigned i1 = base + TPB;

    // Front-batch all global loads (MLP = 4), streaming policy.
    int4   lab0 = __ldcs(&labels4[i0]);
    int4   lab1 = __ldcs(&labels4[i1]);
    float4 p0   = __ldcs(&par4[i0]);
    float4 p1   = __ldcs(&par4[i1]);

    // Per-lane classification, kept in registers after unroll.
    float s0[4], s1[4];
    bool  m0[4], m1[4], d0[4], d1[4];
    #pragma unroll
    for (int k = 0; k < 4; ++k) {
        int l0 = (&lab0.x)[k];
        int l1 = (&lab1.x)[k];
        uint2 e0 = s_lut[l0];
        uint2 e1 = s_lut[l1];
        s0[k] = __uint_as_float(e0.x);   // lut[0] == 1.0 -> branch-free scale
        s1[k] = __uint_as_float(e1.x);
        m0[k] = (l0 != 0);               m1[k] = (l1 != 0);
        d0[k] = m0[k] & (e0.y == 1u);    d1[k] = m1[k] & (e1.y == 1u);
    }

    float4* o4 = (float4*)out;
    float4 a, b;

    // Stream 0: scaled parenchyma (grouped: both tiles back-to-back)
    #pragma unroll
    for (int k = 0; k < 4; ++k) { (&a.x)[k] = (&p0.x)[k] * s0[k];
                                  (&b.x)[k] = (&p1.x)[k] * s1[k]; }
    __stcs(&o4[i0], a);
    __stcs(&o4[i1], b);

    // Stream 1: background channel
    #pragma unroll
    for (int k = 0; k < 4; ++k) { (&a.x)[k] = m0[k] ? 0.0f : 1.0f;
                                  (&b.x)[k] = m1[k] ? 0.0f : 1.0f; }
    __stcs(&o4[VEC + i0], a);
    __stcs(&o4[VEC + i1], b);

    // Stream 2: dark-vessel channel
    #pragma unroll
    for (int k = 0; k < 4; ++k) { (&a.x)[k] = d0[k] ? 1.0f : 0.0f;
                                  (&b.x)[k] = d1[k] ? 1.0f : 0.0f; }
    __stcs(&o4[2u * VEC + i0], a);
    __stcs(&o4[2u * VEC + i1], b);

    // Stream 3: bright-vessel channel
    #pragma unroll
    for (int k = 0; k < 4; ++k) { (&a.x)[k] = (m0[k] & !d0[k]) ? 1.0f : 0.0f;
                                  (&b.x)[k] = (m1[k] & !d1[k]) ? 1.0f : 0.0f; }
    __stcs(&o4[3u * VEC + i0], a);
    __stcs(&o4[3u * VEC + i1], b);
}

extern "C" void kernel_launch(void* const* d_in, const int* in_sizes, int n_in,
                              void* d_out, int out_size)
{
    const int4*   labels4 = (const int4*)d_in[0];
    const float*  id_int  = (const float*)d_in[1];
    const int*    id_dark = (const int*)d_in[2];
    const float4* par4    = (const float4*)d_in[3];
    float*        out     = (float*)d_out;

    yibei_kernel<<<BLOCKS, TPB>>>(labels4, par4, id_int, id_dark, out);
}